// round 5
// baseline (speedup 1.0000x reference)
#include <cuda_runtime.h>
#include <cuda_fp16.h>
#include <cstdint>

// out[b,h,o] = sum_{i,d} x[b,h,i,d] * ws[o,i] * weight[o,d]
// => C (8192x1024) = A (8192x4096, = x viewed row-major fp32) . W2^T
//    W2[n,k] = ws[n,k>>2]*weight[n,k&3]
// Single-term fp16 HMMA GEMM at the legacy mma.sync issue floor (rt~16/SMSP).
// A-conversion fused into the GEMM: cp.async fp32 tiles, per-fragment
// ld.shared.v2.f32 + cvt.rn.f16x2.f32 in the (abundant) spare issue slots.

#define M_DIM 8192
#define N_DIM 1024
#define K_DIM 4096
#define BM 128
#define BN 128
#define BK 32
#define KT (K_DIM / BK)          // 128
#define STAGE_A (128 * 128)      // fp32 A tile: 128 rows x 32 f32 = 16384 B
#define ROWB 80                  // B tile: 32 f16 (64B) + 16B pad
#define TILE_B (128 * ROWB)      // 10240 B
#define STAGE (STAGE_A + TILE_B) // 26624 B
#define NSTAGE 4
#define SMEM_BYTES (NSTAGE * STAGE)   // 106496 B -> 2 CTAs/SM (213 KB)

// Precomputed fp16 W2 (row-major [N][K]).
__device__ __half g_b[(size_t)N_DIM * K_DIM];

// ---------------------------------------------------------------- helpers
__device__ __forceinline__ void ldsm_x4(uint32_t* r, uint32_t addr) {
    asm volatile("ldmatrix.sync.aligned.m8n8.x4.shared.b16 {%0,%1,%2,%3}, [%4];"
                 : "=r"(r[0]), "=r"(r[1]), "=r"(r[2]), "=r"(r[3]) : "r"(addr));
}
__device__ __forceinline__ void mma16816(float* c, const uint32_t* a, const uint32_t* b) {
    asm volatile(
        "mma.sync.aligned.m16n8k16.row.col.f32.f16.f16.f32 "
        "{%0,%1,%2,%3}, {%4,%5,%6,%7}, {%8,%9}, {%0,%1,%2,%3};"
        : "+f"(c[0]), "+f"(c[1]), "+f"(c[2]), "+f"(c[3])
        : "r"(a[0]), "r"(a[1]), "r"(a[2]), "r"(a[3]), "r"(b[0]), "r"(b[1]));
}
__device__ __forceinline__ void cp16(uint32_t dst, const void* src) {
    asm volatile("cp.async.cg.shared.global [%0], [%1], 16;"
                 :: "r"(dst), "l"(src) : "memory");
}
__device__ __forceinline__ uint32_t pack_h2(float a, float b) {
    __half2 h = __floats2half2_rn(a, b);
    return *(uint32_t*)&h;
}
// Load A[row][colbyte..+7] (two f32) from the swizzled fp32 tile, convert to
// one f16x2 fragment register (lo = first element, hi = second).
__device__ __forceinline__ uint32_t a_frag(uint32_t sA, int row, int colbyte) {
    uint32_t addr = sA + (uint32_t)row * 128
                  + ((((uint32_t)colbyte >> 4) ^ ((uint32_t)row & 7)) << 4)
                  + ((uint32_t)colbyte & 15);
    float f0, f1;
    asm volatile("ld.shared.v2.f32 {%0,%1}, [%2];" : "=f"(f0), "=f"(f1) : "r"(addr));
    uint32_t r;
    asm volatile("cvt.rn.f16x2.f32 %0, %1, %2;" : "=r"(r) : "f"(f1), "f"(f0));
    return r;
}

// --------------------------------------- build W2 -> fp16 plane
__global__ __launch_bounds__(256) void convert_w(const float* __restrict__ weight,
                                                 const float* __restrict__ ws) {
    size_t idx = (size_t)blockIdx.x * 256 + threadIdx.x;   // 524,288 threads
    int n  = (int)(idx >> 9);
    int kk = ((int)idx & 511) * 8;     // 8 consecutive k = 2 i-values x 4 d
    int i0 = kk >> 2;
    float2 sv = *(const float2*)(ws + (size_t)n * 1024 + i0);
    float4 wv = *(const float4*)(weight + n * 4);
    uint4 o;
    o.x = pack_h2(sv.x * wv.x, sv.x * wv.y);
    o.y = pack_h2(sv.x * wv.z, sv.x * wv.w);
    o.z = pack_h2(sv.y * wv.x, sv.y * wv.y);
    o.w = pack_h2(sv.y * wv.z, sv.y * wv.w);
    *(uint4*)(g_b + (size_t)n * K_DIM + kk) = o;
}

// ----------------------------------------------------------- fused HMMA GEMM
__global__ __launch_bounds__(256, 2)
void gemm_mma(const float* __restrict__ A, float* __restrict__ out) {
    extern __shared__ uint8_t smem[];
    uint32_t sbase = (uint32_t)__cvta_generic_to_shared(smem);

    const int tid = threadIdx.x, lane = tid & 31, wid = tid >> 5;
    const int wm = wid >> 2;          // 0..1  (64 rows each)
    const int wn = wid & 3;           // 0..3  (32 cols each)
    const int nt = blockIdx.x, mt = blockIdx.y;

    float c[4][4][4];
#pragma unroll
    for (int i = 0; i < 4; i++)
#pragma unroll
        for (int j = 0; j < 4; j++)
#pragma unroll
            for (int q = 0; q < 4; q++) c[i][j][q] = 0.0f;

    const float* asrc = A + (size_t)mt * BM * K_DIM;          // fp32
    const __half* bsrc = g_b + (size_t)nt * BN * K_DIM;        // fp16

    auto issue = [&](int kt) {
        int k0 = kt * BK;
        uint32_t sst = sbase + (kt % NSTAGE) * STAGE;
        // A tile fp32: 128 rows x 8 chunks(16B) = 1024 chunks -> 4 / thread
#pragma unroll
        for (int it = 0; it < 4; it++) {
            int idx = it * 256 + tid;          // 0..1023
            int row = idx >> 3, ch = idx & 7;
            uint32_t dst = sst + row * 128 + (((uint32_t)(ch ^ (row & 7))) << 4);
            cp16(dst, asrc + (size_t)row * K_DIM + k0 + ch * 4);
        }
        // B tile fp16: 128 rows x 4 chunks(16B) = 512 chunks -> 2 / thread
#pragma unroll
        for (int it = 0; it < 2; it++) {
            int idx = it * 256 + tid;
            int row = idx >> 2, ch = idx & 3;
            cp16(sst + STAGE_A + row * ROWB + ch * 16,
                 bsrc + (size_t)row * K_DIM + k0 + ch * 8);
        }
    };

    // fragment addressing (constant per thread)
    const int rA0 = wm * 64 + (lane >> 2);                          // + mf*16 (+8)
    const int cA0 = (lane & 3) * 8;                                 // byte, + ks*64 (+32)
    const int rB = wn * 32 + (lane & 7) + (((lane >> 4) & 1) * 8);  // + nh*16
    const uint32_t kBofs = (((uint32_t)lane >> 3) & 1) * 8;

    // prologue: fill 3 of 4 stages
    issue(0); asm volatile("cp.async.commit_group;" ::: "memory");
    issue(1); asm volatile("cp.async.commit_group;" ::: "memory");
    issue(2); asm volatile("cp.async.commit_group;" ::: "memory");

    for (int kt = 0; kt < KT; kt++) {
        asm volatile("cp.async.wait_group 2;" ::: "memory");
        __syncthreads();

        uint32_t sA = sbase + (kt % NSTAGE) * STAGE;
        uint32_t sB = sA + STAGE_A;

#pragma unroll
        for (int ks = 0; ks < 2; ks++) {
            uint32_t kb = (ks * 16 + kBofs) * 2;
            uint32_t ah[4][4], bh[2][4];
            // A fragments: load fp32 pairs + convert (m16n8k16 layout:
            // a0:(r,k) a1:(r+8,k) a2:(r,k+8) a3:(r+8,k+8))
#pragma unroll
            for (int mf = 0; mf < 4; mf++) {
                int r0 = rA0 + mf * 16;
                int cb = cA0 + ks * 64;
                ah[mf][0] = a_frag(sA, r0,     cb);
                ah[mf][1] = a_frag(sA, r0 + 8, cb);
                ah[mf][2] = a_frag(sA, r0,     cb + 32);
                ah[mf][3] = a_frag(sA, r0 + 8, cb + 32);
            }
#pragma unroll
            for (int nh = 0; nh < 2; nh++)
                ldsm_x4(bh[nh], sB + (uint32_t)(rB + nh * 16) * ROWB + kb);

#pragma unroll
            for (int mf = 0; mf < 4; mf++)
#pragma unroll
                for (int nf = 0; nf < 4; nf++)
                    mma16816(c[mf][nf], ah[mf], &bh[nf >> 1][(nf & 1) * 2]);
        }

        if (kt + 3 < KT) issue(kt + 3);
        asm volatile("cp.async.commit_group;" ::: "memory");
    }

    // ---- epilogue ----
    const int gid = lane >> 2, tig = lane & 3;
#pragma unroll
    for (int mf = 0; mf < 4; mf++) {
#pragma unroll
        for (int nf = 0; nf < 4; nf++) {
            int r0 = mt * BM + wm * 64 + mf * 16 + gid;
            int col = nt * BN + wn * 32 + nf * 8 + tig * 2;
            float* p = out + (size_t)r0 * N_DIM + col;
            *(float2*)p = make_float2(c[mf][nf][0], c[mf][nf][1]);
            *(float2*)(p + 8 * N_DIM) = make_float2(c[mf][nf][2], c[mf][nf][3]);
        }
    }
}

// ---------------------------------------------------------------- launcher
extern "C" void kernel_launch(void* const* d_in, const int* in_sizes, int n_in,
                              void* d_out, int out_size) {
    const float* x      = (const float*)d_in[0];   // (4,2048,1024,4) == A fp32
    const float* weight = (const float*)d_in[1];   // (1024,4)
    const float* ws     = (const float*)d_in[2];   // (1024,1024)
    float* out          = (float*)d_out;           // (4,2048,1024)

    convert_w<<<2048, 256>>>(weight, ws);

    cudaFuncSetAttribute(gemm_mma, cudaFuncAttributeMaxDynamicSharedMemorySize, SMEM_BYTES);
    dim3 grid(N_DIM / BN, M_DIM / BM);   // (8, 64), nt fastest for L2 reuse of A
    gemm_mma<<<grid, 256, SMEM_BYTES>>>(x, out);
}

// round 6
// speedup vs baseline: 1.2268x; 1.2268x over previous
#include <cuda_runtime.h>
#include <cuda_fp16.h>
#include <cstdint>

// out[b,h,o] = sum_{i,d} x[b,h,i,d] * ws[o,i] * weight[o,d]
// => C (8192x1024) = A (8192x4096 fp32 = x) . W2^T,  W2[n,k]=ws[n,k>>2]*weight[n,k&3]
// Single-term fp16 HMMA GEMM. A is converted fp32->fp16 on the register path
// (LDG.128 -> cvt -> STS.64) inside the GEMM, replacing the cp.async A write:
// identical smem crossbar budget to the best kernel, minus the 28us convert_x.

#define M_DIM 8192
#define N_DIM 1024
#define K_DIM 4096
#define BM 128
#define BN 128
#define BK 32
#define KT (K_DIM / BK)        // 128
#define ROWB 80                // 32 f16 (64B) + 16B pad -> conflict-free ldmatrix
#define TILE_B (128 * ROWB)    // 10240 B per tile
#define STAGE (2 * TILE_B)     // A fp16 tile + B fp16 tile = 20480 B
#define NSTAGE 4
#define SMEM_BYTES (NSTAGE * STAGE)   // 81920 B -> 2 CTAs/SM

// Precomputed fp16 W2 (row-major [N][K]).
__device__ __half g_b[(size_t)N_DIM * K_DIM];

// ---------------------------------------------------------------- helpers
__device__ __forceinline__ void ldsm_x4(uint32_t* r, uint32_t addr) {
    asm volatile("ldmatrix.sync.aligned.m8n8.x4.shared.b16 {%0,%1,%2,%3}, [%4];"
                 : "=r"(r[0]), "=r"(r[1]), "=r"(r[2]), "=r"(r[3]) : "r"(addr));
}
__device__ __forceinline__ void mma16816(float* c, const uint32_t* a, const uint32_t* b) {
    asm volatile(
        "mma.sync.aligned.m16n8k16.row.col.f32.f16.f16.f32 "
        "{%0,%1,%2,%3}, {%4,%5,%6,%7}, {%8,%9}, {%0,%1,%2,%3};"
        : "+f"(c[0]), "+f"(c[1]), "+f"(c[2]), "+f"(c[3])
        : "r"(a[0]), "r"(a[1]), "r"(a[2]), "r"(a[3]), "r"(b[0]), "r"(b[1]));
}
__device__ __forceinline__ void cp16(uint32_t dst, const void* src) {
    asm volatile("cp.async.cg.shared.global [%0], [%1], 16;"
                 :: "r"(dst), "l"(src) : "memory");
}
__device__ __forceinline__ uint32_t pack_h2(float a, float b) {
    uint32_t r;
    asm volatile("cvt.rn.f16x2.f32 %0, %1, %2;" : "=r"(r) : "f"(b), "f"(a));
    return r;
}
__device__ __forceinline__ void sts64(uint32_t addr, uint32_t a, uint32_t b) {
    asm volatile("st.shared.v2.u32 [%0], {%1,%2};" :: "r"(addr), "r"(a), "r"(b) : "memory");
}

// --------------------------------------- build W2 -> fp16 plane (tiny, 3us)
__global__ __launch_bounds__(256) void convert_w(const float* __restrict__ weight,
                                                 const float* __restrict__ ws) {
    size_t idx = (size_t)blockIdx.x * 256 + threadIdx.x;   // 524,288 threads
    int n  = (int)(idx >> 9);
    int kk = ((int)idx & 511) * 8;     // 8 consecutive k = 2 i-values x 4 d
    int i0 = kk >> 2;
    float2 sv = *(const float2*)(ws + (size_t)n * 1024 + i0);
    float4 wv = *(const float4*)(weight + n * 4);
    uint4 o;
    o.x = pack_h2(sv.x * wv.x, sv.x * wv.y);
    o.y = pack_h2(sv.x * wv.z, sv.x * wv.w);
    o.z = pack_h2(sv.y * wv.x, sv.y * wv.y);
    o.w = pack_h2(sv.y * wv.z, sv.y * wv.w);
    *(uint4*)(g_b + (size_t)n * K_DIM + kk) = o;
}

// ----------------------------------------------------------- fused HMMA GEMM
__global__ __launch_bounds__(256, 2)
void gemm_mma(const float* __restrict__ A, float* __restrict__ out) {
    extern __shared__ uint8_t smem[];
    uint32_t sbase = (uint32_t)__cvta_generic_to_shared(smem);

    const int tid = threadIdx.x, lane = tid & 31, wid = tid >> 5;
    const int wm = wid >> 2;          // 0..1  (64 rows each)
    const int wn = wid & 3;           // 0..3  (32 cols each)
    const int nt = blockIdx.x, mt = blockIdx.y;

    float c[4][4][4];
#pragma unroll
    for (int i = 0; i < 4; i++)
#pragma unroll
        for (int j = 0; j < 4; j++)
#pragma unroll
            for (int q = 0; q < 4; q++) c[i][j][q] = 0.0f;

    // Per-thread A-conversion addressing: 4 rows (stride 32), 1 fp32 chunk each.
    const int arow0 = tid >> 3;            // 0..31
    const int ach   = tid & 7;             // 0..7 -> 4 floats at col ach*4
    const float* asrc = A + (size_t)mt * BM * K_DIM + (size_t)arow0 * K_DIM + ach * 4;
    const __half* bsrc = g_b + (size_t)nt * BN * K_DIM;

    // Load fp32 A chunk for k-tile kt into regs.
    auto lda = [&](int kt, float4* v) {
        const float* p = asrc + kt * BK;
#pragma unroll
        for (int it = 0; it < 4; it++)
            v[it] = *(const float4*)(p + (size_t)it * 32 * K_DIM);
    };
    // Convert + store into fp16 A tile of stage (kt % NSTAGE).
    auto sta = [&](int kt, const float4* v) {
        uint32_t sst = sbase + (kt % NSTAGE) * STAGE;
#pragma unroll
        for (int it = 0; it < 4; it++) {
            uint32_t dst = sst + (uint32_t)(arow0 + it * 32) * ROWB + ach * 8;
            sts64(dst, pack_h2(v[it].x, v[it].y), pack_h2(v[it].z, v[it].w));
        }
    };
    // B tile via cp.async: 2 chunks of 16B per thread.
    auto issue_b = [&](int kt) {
        int k0 = kt * BK;
        uint32_t sst = sbase + (kt % NSTAGE) * STAGE + TILE_B;
#pragma unroll
        for (int it = 0; it < 2; it++) {
            int idx = it * 256 + tid;
            int row = idx >> 2, ch = idx & 3;
            cp16(sst + row * ROWB + ch * 16,
                 bsrc + (size_t)row * K_DIM + k0 + ch * 8);
        }
    };

    // fragment smem addressing (constant per thread)
    const int rA = wm * 64 + (lane & 15);                          // + mf*16
    const uint32_t kAofs = (((uint32_t)lane >> 4) & 1) * 8;        // + ks*16
    const int rB = wn * 32 + (lane & 7) + (((lane >> 4) & 1) * 8); // + nh*16
    const uint32_t kBofs = (((uint32_t)lane >> 3) & 1) * 8;

    // prologue: A for stages 0,1 via reg path; B groups 0,1 via cp.async
    {
        float4 v[4];
        lda(0, v); sta(0, v);
        lda(1, v); sta(1, v);
    }
    issue_b(0); asm volatile("cp.async.commit_group;" ::: "memory");
    issue_b(1); asm volatile("cp.async.commit_group;" ::: "memory");

    for (int kt = 0; kt < KT; kt++) {
        // keep B pipeline 3 deep; always commit to keep group accounting fixed
        if (kt + 2 < KT) issue_b(kt + 2);
        asm volatile("cp.async.commit_group;" ::: "memory");
        asm volatile("cp.async.wait_group 2;" ::: "memory");
        __syncthreads();

        // A for stage kt+2: LDG early, cvt+STS before compute (regs freed)
        if (kt + 2 < KT) {
            float4 v[4];
            lda(kt + 2, v);
            sta(kt + 2, v);
        }

        uint32_t sA = sbase + (kt % NSTAGE) * STAGE;
        uint32_t sB = sA + TILE_B;

#pragma unroll
        for (int ks = 0; ks < 2; ks++) {
            uint32_t ka = (ks * 16 + kAofs) * 2;
            uint32_t kb = (ks * 16 + kBofs) * 2;
            uint32_t ah[4][4], bh[2][4];
#pragma unroll
            for (int mf = 0; mf < 4; mf++)
                ldsm_x4(ah[mf], sA + (uint32_t)(rA + mf * 16) * ROWB + ka);
#pragma unroll
            for (int nh = 0; nh < 2; nh++)
                ldsm_x4(bh[nh], sB + (uint32_t)(rB + nh * 16) * ROWB + kb);

#pragma unroll
            for (int mf = 0; mf < 4; mf++)
#pragma unroll
                for (int nf = 0; nf < 4; nf++)
                    mma16816(c[mf][nf], ah[mf], &bh[nf >> 1][(nf & 1) * 2]);
        }
    }

    // ---- epilogue ----
    const int gid = lane >> 2, tig = lane & 3;
#pragma unroll
    for (int mf = 0; mf < 4; mf++) {
#pragma unroll
        for (int nf = 0; nf < 4; nf++) {
            int r0 = mt * BM + wm * 64 + mf * 16 + gid;
            int col = nt * BN + wn * 32 + nf * 8 + tig * 2;
            float* p = out + (size_t)r0 * N_DIM + col;
            *(float2*)p = make_float2(c[mf][nf][0], c[mf][nf][1]);
            *(float2*)(p + 8 * N_DIM) = make_float2(c[mf][nf][2], c[mf][nf][3]);
        }
    }
}

// ---------------------------------------------------------------- launcher
extern "C" void kernel_launch(void* const* d_in, const int* in_sizes, int n_in,
                              void* d_out, int out_size) {
    const float* x      = (const float*)d_in[0];   // (4,2048,1024,4) == A fp32
    const float* weight = (const float*)d_in[1];   // (1024,4)
    const float* ws     = (const float*)d_in[2];   // (1024,1024)
    float* out          = (float*)d_out;           // (4,2048,1024)

    convert_w<<<2048, 256>>>(weight, ws);

    cudaFuncSetAttribute(gemm_mma, cudaFuncAttributeMaxDynamicSharedMemorySize, SMEM_BYTES);
    dim3 grid(N_DIM / BN, M_DIM / BM);   // (8, 64), nt fastest for L2 reuse of A
    gemm_mma<<<grid, 256, SMEM_BYTES>>>(x, out);
}

// round 7
// speedup vs baseline: 1.5357x; 1.2518x over previous
#include <cuda_runtime.h>
#include <cuda_fp16.h>
#include <cstdint>

// out[b,h,o] = sum_{i,d} x[b,h,i,d] * ws[o,i] * weight[o,d]
// => C (8192x1024) = A (8192x4096) . W2^T,  W2[n,k] = ws[n,k>>2]*weight[n,k&3]
// Single-term fp16 HMMA GEMM (proven 2.9e-4 rel err). This round: de-phase the
// warps (per-warp ks + ldsm-order stagger) so crossbar and tensor pipes overlap
// instead of alternating in barrier-aligned bursts.

#define M_DIM 8192
#define N_DIM 1024
#define K_DIM 4096
#define BM 128
#define BN 128
#define BK 32
#define KT (K_DIM / BK)        // 128
#define ROWB 80                // 32 f16 (64B) + 16B pad -> conflict-free ldmatrix
#define TILE_B (128 * ROWB)    // 10240 B per tile
#define STAGE (2 * TILE_B)     // A tile + B tile = 20480 B
#define NSTAGE 4
#define SMEM_BYTES (NSTAGE * STAGE)   // 81920 B -> 2 CTAs/SM

// Precomputed fp16 operands (plain row-major).
__device__ __half g_a[(size_t)M_DIM * K_DIM];
__device__ __half g_b[(size_t)N_DIM * K_DIM];

// ---------------------------------------------------------------- helpers
__device__ __forceinline__ void ldsm_x4(uint32_t* r, uint32_t addr) {
    asm volatile("ldmatrix.sync.aligned.m8n8.x4.shared.b16 {%0,%1,%2,%3}, [%4];"
                 : "=r"(r[0]), "=r"(r[1]), "=r"(r[2]), "=r"(r[3]) : "r"(addr));
}
__device__ __forceinline__ void mma16816(float* c, const uint32_t* a, const uint32_t* b) {
    asm volatile(
        "mma.sync.aligned.m16n8k16.row.col.f32.f16.f16.f32 "
        "{%0,%1,%2,%3}, {%4,%5,%6,%7}, {%8,%9}, {%0,%1,%2,%3};"
        : "+f"(c[0]), "+f"(c[1]), "+f"(c[2]), "+f"(c[3])
        : "r"(a[0]), "r"(a[1]), "r"(a[2]), "r"(a[3]), "r"(b[0]), "r"(b[1]));
}
__device__ __forceinline__ void cp16(uint32_t dst, const void* src) {
    asm volatile("cp.async.cg.shared.global [%0], [%1], 16;"
                 :: "r"(dst), "l"(src) : "memory");
}
__device__ __forceinline__ uint32_t pack_h2(float a, float b) {
    uint32_t r;
    asm volatile("cvt.rn.f16x2.f32 %0, %1, %2;" : "=r"(r) : "f"(b), "f"(a));
    return r;
}

// ------------------------------------------------- convert x -> fp16 plane
__global__ __launch_bounds__(256) void convert_x(const float* __restrict__ x) {
    size_t idx = (size_t)blockIdx.x * 256 + threadIdx.x;   // 4,194,304 threads
    size_t base = idx * 8;
    float4 t0 = *(const float4*)(x + base);
    float4 t1 = *(const float4*)(x + base + 4);
    uint4 o;
    o.x = pack_h2(t0.x, t0.y);
    o.y = pack_h2(t0.z, t0.w);
    o.z = pack_h2(t1.x, t1.y);
    o.w = pack_h2(t1.z, t1.w);
    *(uint4*)(g_a + base) = o;
}

// --------------------------------------- build W2 -> fp16 plane
__global__ __launch_bounds__(256) void convert_w(const float* __restrict__ weight,
                                                 const float* __restrict__ ws) {
    size_t idx = (size_t)blockIdx.x * 256 + threadIdx.x;   // 524,288 threads
    int n  = (int)(idx >> 9);
    int kk = ((int)idx & 511) * 8;     // 8 consecutive k = 2 i-values x 4 d
    int i0 = kk >> 2;
    float2 sv = *(const float2*)(ws + (size_t)n * 1024 + i0);
    float4 wv = *(const float4*)(weight + n * 4);
    uint4 o;
    o.x = pack_h2(sv.x * wv.x, sv.x * wv.y);
    o.y = pack_h2(sv.x * wv.z, sv.x * wv.w);
    o.z = pack_h2(sv.y * wv.x, sv.y * wv.y);
    o.w = pack_h2(sv.y * wv.z, sv.y * wv.w);
    *(uint4*)(g_b + (size_t)n * K_DIM + kk) = o;
}

// ----------------------------------------------------------- HMMA GEMM
__global__ __launch_bounds__(256, 2)
void gemm_mma(float* __restrict__ out) {
    extern __shared__ uint8_t smem[];
    uint32_t sbase = (uint32_t)__cvta_generic_to_shared(smem);

    const int tid = threadIdx.x, lane = tid & 31, wid = tid >> 5;
    const int wm = wid >> 2;          // 0..1  (64 rows each)
    const int wn = wid & 3;           // 0..3  (32 cols each)
    const int wpar = wid & 1;         // stagger parity
    const int nt = blockIdx.x, mt = blockIdx.y;

    float c[4][4][4];
#pragma unroll
    for (int i = 0; i < 4; i++)
#pragma unroll
        for (int j = 0; j < 4; j++)
#pragma unroll
            for (int q = 0; q < 4; q++) c[i][j][q] = 0.0f;

    const __half* asrc = g_a + (size_t)mt * BM * K_DIM;
    const __half* bsrc = g_b + (size_t)nt * BN * K_DIM;

    auto issue = [&](int kt) {
        int k0 = kt * BK;
        uint32_t sst = sbase + (kt % NSTAGE) * STAGE;
#pragma unroll
        for (int it = 0; it < 2; it++) {
            int idx = it * 256 + tid;          // 0..511
            int row = idx >> 2, ch = idx & 3;  // 128 rows x 4 chunks
            cp16(sst + row * ROWB + ch * 16,
                 asrc + (size_t)row * K_DIM + k0 + ch * 8);
        }
#pragma unroll
        for (int it = 0; it < 2; it++) {
            int idx = it * 256 + tid;
            int row = idx >> 2, ch = idx & 3;
            cp16(sst + TILE_B + row * ROWB + ch * 16,
                 bsrc + (size_t)row * K_DIM + k0 + ch * 8);
        }
    };

    // fragment smem addressing (constant per thread)
    const int rA = wm * 64 + (lane & 15);                          // + mf*16
    const uint32_t kAofs = (((uint32_t)lane >> 4) & 1) * 8;        // + ks*16
    const int rB = wn * 32 + (lane & 7) + (((lane >> 4) & 1) * 8); // + nh*16
    const uint32_t kBofs = (((uint32_t)lane >> 3) & 1) * 8;

    // prologue: fill 3 of 4 stages
    issue(0); asm volatile("cp.async.commit_group;" ::: "memory");
    issue(1); asm volatile("cp.async.commit_group;" ::: "memory");
    issue(2); asm volatile("cp.async.commit_group;" ::: "memory");

    for (int kt = 0; kt < KT; kt++) {
        asm volatile("cp.async.wait_group 2;" ::: "memory");
        __syncthreads();

        uint32_t sA = sbase + (kt % NSTAGE) * STAGE;
        uint32_t sB = sA + TILE_B;

#pragma unroll
        for (int ks2 = 0; ks2 < 2; ks2++) {
            // de-phase: odd warps walk ks in the opposite order, so at any
            // instant ~half the warps are in ldsm while half are in mma.
            int ks = ks2 ^ wpar;
            uint32_t ka = (ks * 16 + kAofs) * 2;
            uint32_t kb = (ks * 16 + kBofs) * 2;
            uint32_t ah[4][4], bh[2][4];
            if (wpar == 0) {
#pragma unroll
                for (int mf = 0; mf < 4; mf++)
                    ldsm_x4(ah[mf], sA + (uint32_t)(rA + mf * 16) * ROWB + ka);
#pragma unroll
                for (int nh = 0; nh < 2; nh++)
                    ldsm_x4(bh[nh], sB + (uint32_t)(rB + nh * 16) * ROWB + kb);
            } else {
#pragma unroll
                for (int nh = 0; nh < 2; nh++)
                    ldsm_x4(bh[nh], sB + (uint32_t)(rB + nh * 16) * ROWB + kb);
#pragma unroll
                for (int mf = 0; mf < 4; mf++)
                    ldsm_x4(ah[mf], sA + (uint32_t)(rA + mf * 16) * ROWB + ka);
            }

#pragma unroll
            for (int mf = 0; mf < 4; mf++)
#pragma unroll
                for (int nf = 0; nf < 4; nf++)
                    mma16816(c[mf][nf], ah[mf], &bh[nf >> 1][(nf & 1) * 2]);
        }

        if (kt + 3 < KT) issue(kt + 3);
        asm volatile("cp.async.commit_group;" ::: "memory");
    }

    // ---- epilogue ----
    const int gid = lane >> 2, tig = lane & 3;
#pragma unroll
    for (int mf = 0; mf < 4; mf++) {
#pragma unroll
        for (int nf = 0; nf < 4; nf++) {
            int r0 = mt * BM + wm * 64 + mf * 16 + gid;
            int col = nt * BN + wn * 32 + nf * 8 + tig * 2;
            float* p = out + (size_t)r0 * N_DIM + col;
            *(float2*)p = make_float2(c[mf][nf][0], c[mf][nf][1]);
            *(float2*)(p + 8 * N_DIM) = make_float2(c[mf][nf][2], c[mf][nf][3]);
        }
    }
}

// ---------------------------------------------------------------- launcher
extern "C" void kernel_launch(void* const* d_in, const int* in_sizes, int n_in,
                              void* d_out, int out_size) {
    const float* x      = (const float*)d_in[0];   // (4,2048,1024,4)
    const float* weight = (const float*)d_in[1];   // (1024,4)
    const float* ws     = (const float*)d_in[2];   // (1024,1024)
    float* out          = (float*)d_out;           // (4,2048,1024)

    convert_x<<<16384, 256>>>(x);
    convert_w<<<2048, 256>>>(weight, ws);

    cudaFuncSetAttribute(gemm_mma, cudaFuncAttributeMaxDynamicSharedMemorySize, SMEM_BYTES);
    dim3 grid(N_DIM / BN, M_DIM / BM);   // (8, 64), nt fastest for L2 reuse of A
    gemm_mma<<<grid, 256, SMEM_BYTES>>>(out);
}

// round 8
// speedup vs baseline: 1.5378x; 1.0014x over previous
#include <cuda_runtime.h>
#include <cuda_fp16.h>
#include <cstdint>

// out[b,h,o] = sum_{i,d} x[b,h,i,d] * ws[o,i] * weight[o,d]
// => C (8192x1024) = A (8192x4096) . W2^T,  W2[n,k] = ws[n,k>>2]*weight[n,k&3]
// Single-term fp16 HMMA GEMM. This round: dependency-ordered inner loop --
// B fragments first, then A row-by-row interleaved with that row's mmas, so
// the tensor pipe starts ~3 ldsm into the burst instead of after all 12.

#define M_DIM 8192
#define N_DIM 1024
#define K_DIM 4096
#define BM 128
#define BN 128
#define BK 32
#define KT (K_DIM / BK)        // 128
#define ROWB 80                // 32 f16 (64B) + 16B pad -> conflict-free ldmatrix
#define TILE_B (128 * ROWB)    // 10240 B per tile
#define STAGE (2 * TILE_B)     // A tile + B tile = 20480 B
#define NSTAGE 4
#define SMEM_BYTES (NSTAGE * STAGE)   // 81920 B -> 2 CTAs/SM

// Precomputed fp16 operands (plain row-major).
__device__ __half g_a[(size_t)M_DIM * K_DIM];
__device__ __half g_b[(size_t)N_DIM * K_DIM];

// ---------------------------------------------------------------- helpers
__device__ __forceinline__ void ldsm_x4(uint32_t* r, uint32_t addr) {
    asm volatile("ldmatrix.sync.aligned.m8n8.x4.shared.b16 {%0,%1,%2,%3}, [%4];"
                 : "=r"(r[0]), "=r"(r[1]), "=r"(r[2]), "=r"(r[3]) : "r"(addr));
}
__device__ __forceinline__ void mma16816(float* c, const uint32_t* a, const uint32_t* b) {
    asm volatile(
        "mma.sync.aligned.m16n8k16.row.col.f32.f16.f16.f32 "
        "{%0,%1,%2,%3}, {%4,%5,%6,%7}, {%8,%9}, {%0,%1,%2,%3};"
        : "+f"(c[0]), "+f"(c[1]), "+f"(c[2]), "+f"(c[3])
        : "r"(a[0]), "r"(a[1]), "r"(a[2]), "r"(a[3]), "r"(b[0]), "r"(b[1]));
}
__device__ __forceinline__ void cp16(uint32_t dst, const void* src) {
    asm volatile("cp.async.cg.shared.global [%0], [%1], 16;"
                 :: "r"(dst), "l"(src) : "memory");
}
__device__ __forceinline__ uint32_t pack_h2(float a, float b) {
    uint32_t r;
    asm volatile("cvt.rn.f16x2.f32 %0, %1, %2;" : "=r"(r) : "f"(b), "f"(a));
    return r;
}

// ------------------------------------------------- convert x -> fp16 plane
__global__ __launch_bounds__(256) void convert_x(const float* __restrict__ x) {
    size_t idx = (size_t)blockIdx.x * 256 + threadIdx.x;   // 4,194,304 threads
    size_t base = idx * 8;
    float4 t0 = *(const float4*)(x + base);
    float4 t1 = *(const float4*)(x + base + 4);
    uint4 o;
    o.x = pack_h2(t0.x, t0.y);
    o.y = pack_h2(t0.z, t0.w);
    o.z = pack_h2(t1.x, t1.y);
    o.w = pack_h2(t1.z, t1.w);
    *(uint4*)(g_a + base) = o;
}

// --------------------------------------- build W2 -> fp16 plane
__global__ __launch_bounds__(256) void convert_w(const float* __restrict__ weight,
                                                 const float* __restrict__ ws) {
    size_t idx = (size_t)blockIdx.x * 256 + threadIdx.x;   // 524,288 threads
    int n  = (int)(idx >> 9);
    int kk = ((int)idx & 511) * 8;     // 8 consecutive k = 2 i-values x 4 d
    int i0 = kk >> 2;
    float2 sv = *(const float2*)(ws + (size_t)n * 1024 + i0);
    float4 wv = *(const float4*)(weight + n * 4);
    uint4 o;
    o.x = pack_h2(sv.x * wv.x, sv.x * wv.y);
    o.y = pack_h2(sv.x * wv.z, sv.x * wv.w);
    o.z = pack_h2(sv.y * wv.x, sv.y * wv.y);
    o.w = pack_h2(sv.y * wv.z, sv.y * wv.w);
    *(uint4*)(g_b + (size_t)n * K_DIM + kk) = o;
}

// ----------------------------------------------------------- HMMA GEMM
__global__ __launch_bounds__(256, 2)
void gemm_mma(float* __restrict__ out) {
    extern __shared__ uint8_t smem[];
    uint32_t sbase = (uint32_t)__cvta_generic_to_shared(smem);

    const int tid = threadIdx.x, lane = tid & 31, wid = tid >> 5;
    const int wm = wid >> 2;          // 0..1  (64 rows each)
    const int wn = wid & 3;           // 0..3  (32 cols each)
    const int nt = blockIdx.x, mt = blockIdx.y;

    float c[4][4][4];
#pragma unroll
    for (int i = 0; i < 4; i++)
#pragma unroll
        for (int j = 0; j < 4; j++)
#pragma unroll
            for (int q = 0; q < 4; q++) c[i][j][q] = 0.0f;

    const __half* asrc = g_a + (size_t)mt * BM * K_DIM;
    const __half* bsrc = g_b + (size_t)nt * BN * K_DIM;

    auto issue = [&](int kt) {
        int k0 = kt * BK;
        uint32_t sst = sbase + (kt % NSTAGE) * STAGE;
#pragma unroll
        for (int it = 0; it < 2; it++) {
            int idx = it * 256 + tid;          // 0..511
            int row = idx >> 2, ch = idx & 3;  // 128 rows x 4 chunks
            cp16(sst + row * ROWB + ch * 16,
                 asrc + (size_t)row * K_DIM + k0 + ch * 8);
        }
#pragma unroll
        for (int it = 0; it < 2; it++) {
            int idx = it * 256 + tid;
            int row = idx >> 2, ch = idx & 3;
            cp16(sst + TILE_B + row * ROWB + ch * 16,
                 bsrc + (size_t)row * K_DIM + k0 + ch * 8);
        }
    };

    // fragment smem addressing (constant per thread)
    const int rA = wm * 64 + (lane & 15);                          // + mf*16
    const uint32_t kAofs = (((uint32_t)lane >> 4) & 1) * 8;        // + ks*16
    const int rB = wn * 32 + (lane & 7) + (((lane >> 4) & 1) * 8); // + nh*16
    const uint32_t kBofs = (((uint32_t)lane >> 3) & 1) * 8;

    // prologue: fill 3 of 4 stages
    issue(0); asm volatile("cp.async.commit_group;" ::: "memory");
    issue(1); asm volatile("cp.async.commit_group;" ::: "memory");
    issue(2); asm volatile("cp.async.commit_group;" ::: "memory");

    for (int kt = 0; kt < KT; kt++) {
        asm volatile("cp.async.wait_group 2;" ::: "memory");
        __syncthreads();

        uint32_t sA = sbase + (kt % NSTAGE) * STAGE;
        uint32_t sB = sA + TILE_B;

#pragma unroll
        for (int ks = 0; ks < 2; ks++) {
            uint32_t ka = (ks * 16 + kAofs) * 2;
            uint32_t kb = (ks * 16 + kBofs) * 2;
            uint32_t ah[4][4], bh[2][4];
            // dependency-ordered: B first (first mma needs bh[0]), then A
            // row 0; subsequent A rows load UNDER the previous row's mmas.
            ldsm_x4(bh[0], sB + (uint32_t)(rB) * ROWB + kb);
            ldsm_x4(bh[1], sB + (uint32_t)(rB + 16) * ROWB + kb);
            ldsm_x4(ah[0], sA + (uint32_t)(rA) * ROWB + ka);
#pragma unroll
            for (int mf = 0; mf < 4; mf++) {
                if (mf < 3)
                    ldsm_x4(ah[mf + 1], sA + (uint32_t)(rA + (mf + 1) * 16) * ROWB + ka);
#pragma unroll
                for (int nf = 0; nf < 4; nf++)
                    mma16816(c[mf][nf], ah[mf], &bh[nf >> 1][(nf & 1) * 2]);
            }
        }

        if (kt + 3 < KT) issue(kt + 3);
        asm volatile("cp.async.commit_group;" ::: "memory");
    }

    // ---- epilogue ----
    const int gid = lane >> 2, tig = lane & 3;
#pragma unroll
    for (int mf = 0; mf < 4; mf++) {
#pragma unroll
        for (int nf = 0; nf < 4; nf++) {
            int r0 = mt * BM + wm * 64 + mf * 16 + gid;
            int col = nt * BN + wn * 32 + nf * 8 + tig * 2;
            float* p = out + (size_t)r0 * N_DIM + col;
            *(float2*)p = make_float2(c[mf][nf][0], c[mf][nf][1]);
            *(float2*)(p + 8 * N_DIM) = make_float2(c[mf][nf][2], c[mf][nf][3]);
        }
    }
}

// ---------------------------------------------------------------- launcher
extern "C" void kernel_launch(void* const* d_in, const int* in_sizes, int n_in,
                              void* d_out, int out_size) {
    const float* x      = (const float*)d_in[0];   // (4,2048,1024,4)
    const float* weight = (const float*)d_in[1];   // (1024,4)
    const float* ws     = (const float*)d_in[2];   // (1024,1024)
    float* out          = (float*)d_out;           // (4,2048,1024)

    convert_x<<<16384, 256>>>(x);
    convert_w<<<2048, 256>>>(weight, ws);

    cudaFuncSetAttribute(gemm_mma, cudaFuncAttributeMaxDynamicSharedMemorySize, SMEM_BYTES);
    dim3 grid(N_DIM / BN, M_DIM / BM);   // (8, 64), nt fastest for L2 reuse of A
    gemm_mma<<<grid, 256, SMEM_BYTES>>>(out);
}

// round 9
// speedup vs baseline: 1.8706x; 1.2164x over previous
#include <cuda_runtime.h>
#include <cuda_fp16.h>
#include <cstdint>

// out[b,h,o] = sum_{i,d} x[b,h,i,d] * ws[o,i] * weight[o,d]
// => C (8192x1024) = A (8192x4096) . W2^T,  W2[n,k] = ws[n,k>>2]*weight[n,k&3]
// Single-term fp16 HMMA GEMM. This round: 2x2 warp grid of 64x64 warp tiles
// (4 warps/CTA) -- smem read traffic per iter drops 48KB -> 32KB, moving the
// kernel from crossbar+tensor co-bound to tensor-bound with crossbar slack.

#define M_DIM 8192
#define N_DIM 1024
#define K_DIM 4096
#define BM 128
#define BN 128
#define BK 32
#define KT (K_DIM / BK)        // 128
#define ROWB 80                // 32 f16 (64B) + 16B pad -> conflict-free ldmatrix
#define TILE_B (128 * ROWB)    // 10240 B per tile
#define STAGE (2 * TILE_B)     // A tile + B tile = 20480 B
#define NSTAGE 4
#define SMEM_BYTES (NSTAGE * STAGE)   // 81920 B -> 2 CTAs/SM

// Precomputed fp16 operands (plain row-major).
__device__ __half g_a[(size_t)M_DIM * K_DIM];
__device__ __half g_b[(size_t)N_DIM * K_DIM];

// ---------------------------------------------------------------- helpers
__device__ __forceinline__ void ldsm_x4(uint32_t* r, uint32_t addr) {
    asm volatile("ldmatrix.sync.aligned.m8n8.x4.shared.b16 {%0,%1,%2,%3}, [%4];"
                 : "=r"(r[0]), "=r"(r[1]), "=r"(r[2]), "=r"(r[3]) : "r"(addr));
}
__device__ __forceinline__ void mma16816(float* c, const uint32_t* a, const uint32_t* b) {
    asm volatile(
        "mma.sync.aligned.m16n8k16.row.col.f32.f16.f16.f32 "
        "{%0,%1,%2,%3}, {%4,%5,%6,%7}, {%8,%9}, {%0,%1,%2,%3};"
        : "+f"(c[0]), "+f"(c[1]), "+f"(c[2]), "+f"(c[3])
        : "r"(a[0]), "r"(a[1]), "r"(a[2]), "r"(a[3]), "r"(b[0]), "r"(b[1]));
}
__device__ __forceinline__ void cp16(uint32_t dst, const void* src) {
    asm volatile("cp.async.cg.shared.global [%0], [%1], 16;"
                 :: "r"(dst), "l"(src) : "memory");
}
__device__ __forceinline__ uint32_t pack_h2(float a, float b) {
    uint32_t r;
    asm volatile("cvt.rn.f16x2.f32 %0, %1, %2;" : "=r"(r) : "f"(b), "f"(a));
    return r;
}

// ------------------------------------------------- convert x -> fp16 plane
__global__ __launch_bounds__(256) void convert_x(const float* __restrict__ x) {
    size_t idx = (size_t)blockIdx.x * 256 + threadIdx.x;   // 4,194,304 threads
    size_t base = idx * 8;
    float4 t0 = *(const float4*)(x + base);
    float4 t1 = *(const float4*)(x + base + 4);
    uint4 o;
    o.x = pack_h2(t0.x, t0.y);
    o.y = pack_h2(t0.z, t0.w);
    o.z = pack_h2(t1.x, t1.y);
    o.w = pack_h2(t1.z, t1.w);
    *(uint4*)(g_a + base) = o;
}

// --------------------------------------- build W2 -> fp16 plane
__global__ __launch_bounds__(256) void convert_w(const float* __restrict__ weight,
                                                 const float* __restrict__ ws) {
    size_t idx = (size_t)blockIdx.x * 256 + threadIdx.x;   // 524,288 threads
    int n  = (int)(idx >> 9);
    int kk = ((int)idx & 511) * 8;     // 8 consecutive k = 2 i-values x 4 d
    int i0 = kk >> 2;
    float2 sv = *(const float2*)(ws + (size_t)n * 1024 + i0);
    float4 wv = *(const float4*)(weight + n * 4);
    uint4 o;
    o.x = pack_h2(sv.x * wv.x, sv.x * wv.y);
    o.y = pack_h2(sv.x * wv.z, sv.x * wv.w);
    o.z = pack_h2(sv.y * wv.x, sv.y * wv.y);
    o.w = pack_h2(sv.y * wv.z, sv.y * wv.w);
    *(uint4*)(g_b + (size_t)n * K_DIM + kk) = o;
}

// ----------------------------------------------------------- HMMA GEMM
__global__ __launch_bounds__(128, 2)
void gemm_mma(float* __restrict__ out) {
    extern __shared__ uint8_t smem[];
    uint32_t sbase = (uint32_t)__cvta_generic_to_shared(smem);

    const int tid = threadIdx.x, lane = tid & 31, wid = tid >> 5;
    const int wm = wid >> 1;          // 0..1  (64 rows)
    const int wn = wid & 1;           // 0..1  (64 cols)
    const int nt = blockIdx.x, mt = blockIdx.y;

    float c[4][8][4];
#pragma unroll
    for (int i = 0; i < 4; i++)
#pragma unroll
        for (int j = 0; j < 8; j++)
#pragma unroll
            for (int q = 0; q < 4; q++) c[i][j][q] = 0.0f;

    const __half* asrc = g_a + (size_t)mt * BM * K_DIM;
    const __half* bsrc = g_b + (size_t)nt * BN * K_DIM;

    auto issue = [&](int kt) {
        int k0 = kt * BK;
        uint32_t sst = sbase + (kt % NSTAGE) * STAGE;
#pragma unroll
        for (int it = 0; it < 4; it++) {
            int idx = it * 128 + tid;          // 0..511
            int row = idx >> 2, ch = idx & 3;  // 128 rows x 4 chunks
            cp16(sst + row * ROWB + ch * 16,
                 asrc + (size_t)row * K_DIM + k0 + ch * 8);
        }
#pragma unroll
        for (int it = 0; it < 4; it++) {
            int idx = it * 128 + tid;
            int row = idx >> 2, ch = idx & 3;
            cp16(sst + TILE_B + row * ROWB + ch * 16,
                 bsrc + (size_t)row * K_DIM + k0 + ch * 8);
        }
    };

    // fragment smem addressing (constant per thread)
    const int rA = wm * 64 + (lane & 15);                          // + mf*16
    const uint32_t kAofs = (((uint32_t)lane >> 4) & 1) * 8;        // + ks*16
    const int rB = wn * 64 + (lane & 7) + (((lane >> 4) & 1) * 8); // + nh*16
    const uint32_t kBofs = (((uint32_t)lane >> 3) & 1) * 8;

    // prologue: fill 3 of 4 stages
    issue(0); asm volatile("cp.async.commit_group;" ::: "memory");
    issue(1); asm volatile("cp.async.commit_group;" ::: "memory");
    issue(2); asm volatile("cp.async.commit_group;" ::: "memory");

    for (int kt = 0; kt < KT; kt++) {
        asm volatile("cp.async.wait_group 2;" ::: "memory");
        __syncthreads();

        uint32_t sA = sbase + (kt % NSTAGE) * STAGE;
        uint32_t sB = sA + TILE_B;

#pragma unroll
        for (int ks = 0; ks < 2; ks++) {
            uint32_t ka = (ks * 16 + kAofs) * 2;
            uint32_t kb = (ks * 16 + kBofs) * 2;
            uint32_t ah[4][4], bh[4][4];
#pragma unroll
            for (int nh = 0; nh < 4; nh++)
                ldsm_x4(bh[nh], sB + (uint32_t)(rB + nh * 16) * ROWB + kb);
#pragma unroll
            for (int mf = 0; mf < 4; mf++)
                ldsm_x4(ah[mf], sA + (uint32_t)(rA + mf * 16) * ROWB + ka);

#pragma unroll
            for (int mf = 0; mf < 4; mf++)
#pragma unroll
                for (int nf = 0; nf < 8; nf++)
                    mma16816(c[mf][nf], ah[mf], &bh[nf >> 1][(nf & 1) * 2]);
        }

        if (kt + 3 < KT) issue(kt + 3);
        asm volatile("cp.async.commit_group;" ::: "memory");
    }

    // ---- epilogue ----
    const int gid = lane >> 2, tig = lane & 3;
#pragma unroll
    for (int mf = 0; mf < 4; mf++) {
#pragma unroll
        for (int nf = 0; nf < 8; nf++) {
            int r0 = mt * BM + wm * 64 + mf * 16 + gid;
            int col = nt * BN + wn * 64 + nf * 8 + tig * 2;
            float* p = out + (size_t)r0 * N_DIM + col;
            *(float2*)p = make_float2(c[mf][nf][0], c[mf][nf][1]);
            *(float2*)(p + 8 * N_DIM) = make_float2(c[mf][nf][2], c[mf][nf][3]);
        }
    }
}

// ---------------------------------------------------------------- launcher
extern "C" void kernel_launch(void* const* d_in, const int* in_sizes, int n_in,
                              void* d_out, int out_size) {
    const float* x      = (const float*)d_in[0];   // (4,2048,1024,4)
    const float* weight = (const float*)d_in[1];   // (1024,4)
    const float* ws     = (const float*)d_in[2];   // (1024,1024)
    float* out          = (float*)d_out;           // (4,2048,1024)

    convert_x<<<16384, 256>>>(x);
    convert_w<<<2048, 256>>>(weight, ws);

    cudaFuncSetAttribute(gemm_mma, cudaFuncAttributeMaxDynamicSharedMemorySize, SMEM_BYTES);
    dim3 grid(N_DIM / BN, M_DIM / BM);   // (8, 64), nt fastest for L2 reuse of A
    gemm_mma<<<grid, 128, SMEM_BYTES>>>(out);
}